// round 2
// baseline (speedup 1.0000x reference)
#include <cuda_runtime.h>
#include <math.h>

// ---------------------------------------------------------------------------
// SANet attention block, fp32.
//   f = conv1x1(content, f_w, f_b)                      (B, 64, 4096)
//   xr = bilinear_resize(style, 64, 64)                 (B, 512, 4096)
//   g = conv1x1(xr, g_w, g_b)                           (B, 64, 4096)
//   h = conv1x1(xr, h_w, h_b)                           (B, 512, 4096)
//   S[m][n] = sum_c f[c][m] g[c][n]; P = softmax_n(S)   (B, 4096, 4096)
//   o[c][m] = sum_n h[c][n] P[m][n]                     (B, 512, 4096)
//   out = conv1x1(o, out_w, out_b)                      (B, 512, 64, 64)
// resize(conv(x)) == conv(resize(x)) (both linear), so g/h convs run on xr.
// ---------------------------------------------------------------------------

#define BATCH 4
#define CIN   512
#define C8    64
#define HW    4096
#define SHW   6400   // 80*80

// Scratch (allocation-free: __device__ globals)
__device__ float g_xr[(size_t)BATCH * CIN * HW];   // 33.5 MB
__device__ float g_f [(size_t)BATCH * C8  * HW];   //  4.2 MB
__device__ float g_g [(size_t)BATCH * C8  * HW];   //  4.2 MB
__device__ float g_h [(size_t)BATCH * CIN * HW];   // 33.5 MB
__device__ float g_S [(size_t)BATCH * HW  * HW];   // 268 MB
__device__ float g_o [(size_t)BATCH * CIN * HW];   // 33.5 MB

// ---------------------------------------------------------------------------
// Bilinear resize 80x80 -> 64x64 over (B*C) planes.
// ---------------------------------------------------------------------------
__global__ __launch_bounds__(256) void resize_kernel(
    const float* __restrict__ style, float* __restrict__ xr)
{
    long idx = (long)blockIdx.x * blockDim.x + threadIdx.x; // B*CIN*HW threads
    int m      = (int)(idx & (HW - 1));
    long plane = idx >> 12;
    int x = m & 63, y = m >> 6;

    float sy = fmaxf((y + 0.5f) * 1.25f - 0.5f, 0.0f);
    int   y0 = (int)sy;
    int   y1 = min(y0 + 1, 79);
    float wy = sy - (float)y0;
    float sx = fmaxf((x + 0.5f) * 1.25f - 0.5f, 0.0f);
    int   x0 = (int)sx;
    int   x1 = min(x0 + 1, 79);
    float wx = sx - (float)x0;

    const float* p = style + plane * SHW;
    float top = p[y0 * 80 + x0] * (1.0f - wx) + p[y0 * 80 + x1] * wx;
    float bot = p[y1 * 80 + x0] * (1.0f - wx) + p[y1 * 80 + x1] * wx;
    xr[idx] = top * (1.0f - wy) + bot * wy;
}

// ---------------------------------------------------------------------------
// 64x128x16 SGEMM (for the small M=64 f/g convs).
//   C[M][N] = sum_k opA(k,m) * opB(k,n) (+ bias[m])
// ---------------------------------------------------------------------------
#define GBM 64
#define GBN 128
#define GBK 16

template <bool A_KM, bool B_KN, bool HAS_BIAS>
__global__ __launch_bounds__(256) void gemm64_kernel(
    const float* __restrict__ A, const float* __restrict__ B,
    float* __restrict__ C, const float* __restrict__ bias,
    int M, int N, int K,
    long long strideA, long long strideB, long long strideC)
{
    A += (long long)blockIdx.z * strideA;
    B += (long long)blockIdx.z * strideB;
    C += (long long)blockIdx.z * strideC;

    const int bm = blockIdx.y * GBM;
    const int bn = blockIdx.x * GBN;

    __shared__ float As[GBK][GBM];
    __shared__ float Bs[GBK][GBN];

    const int tid = threadIdx.x;
    const int tx = tid & 15;
    const int ty = tid >> 4;

    float acc[4][8];
#pragma unroll
    for (int i = 0; i < 4; i++)
#pragma unroll
        for (int j = 0; j < 8; j++) acc[i][j] = 0.0f;

    for (int k0 = 0; k0 < K; k0 += GBK) {
        if (A_KM) {
            int k  = tid >> 4;
            int m4 = (tid & 15) << 2;
            float4 v = *(const float4*)(A + (long)(k0 + k) * M + bm + m4);
            *(float4*)&As[k][m4] = v;
        } else {
            int m  = tid >> 2;
            int k4 = (tid & 3) << 2;
            float4 v = *(const float4*)(A + (long)(bm + m) * K + k0 + k4);
            As[k4 + 0][m] = v.x; As[k4 + 1][m] = v.y;
            As[k4 + 2][m] = v.z; As[k4 + 3][m] = v.w;
        }
        if (B_KN) {
            int f4 = tid * 2;
            int kr0 = f4 >> 5, c0 = (f4 & 31) << 2;
            *(float4*)&Bs[kr0][c0] =
                *(const float4*)(B + (long)(k0 + kr0) * N + bn + c0);
            int f41 = f4 + 1;
            int kr1 = f41 >> 5, c1 = (f41 & 31) << 2;
            *(float4*)&Bs[kr1][c1] =
                *(const float4*)(B + (long)(k0 + kr1) * N + bn + c1);
        } else {
            int n  = tid >> 1;
            int k8 = (tid & 1) << 3;
            float4 v0 = *(const float4*)(B + (long)(bn + n) * K + k0 + k8);
            float4 v1 = *(const float4*)(B + (long)(bn + n) * K + k0 + k8 + 4);
            Bs[k8 + 0][n] = v0.x; Bs[k8 + 1][n] = v0.y;
            Bs[k8 + 2][n] = v0.z; Bs[k8 + 3][n] = v0.w;
            Bs[k8 + 4][n] = v1.x; Bs[k8 + 5][n] = v1.y;
            Bs[k8 + 6][n] = v1.z; Bs[k8 + 7][n] = v1.w;
        }
        __syncthreads();

#pragma unroll
        for (int kk = 0; kk < GBK; kk++) {
            float a[4], b[8];
            *(float4*)a     = *(float4*)&As[kk][ty << 2];
            *(float4*)&b[0] = *(float4*)&Bs[kk][tx << 2];
            *(float4*)&b[4] = *(float4*)&Bs[kk][64 + (tx << 2)];
#pragma unroll
            for (int i = 0; i < 4; i++)
#pragma unroll
                for (int j = 0; j < 8; j++) acc[i][j] += a[i] * b[j];
        }
        __syncthreads();
    }

#pragma unroll
    for (int i = 0; i < 4; i++) {
        int m = bm + (ty << 2) + i;
        float bv = HAS_BIAS ? bias[m] : 0.0f;
        long rowoff = (long)m * N;
        float4 v0, v1;
        v0.x = acc[i][0] + bv; v0.y = acc[i][1] + bv;
        v0.z = acc[i][2] + bv; v0.w = acc[i][3] + bv;
        v1.x = acc[i][4] + bv; v1.y = acc[i][5] + bv;
        v1.z = acc[i][6] + bv; v1.w = acc[i][7] + bv;
        *(float4*)(C + rowoff + bn + (tx << 2))      = v0;
        *(float4*)(C + rowoff + bn + 64 + (tx << 2)) = v1;
    }
}

// ---------------------------------------------------------------------------
// 128x128x16 SGEMM, 256 threads, 8x8 microtile (2x2 of float4 fragments).
//   C[M][N] = sum_k opA(k,m) * opB(k,n) (+ bias[m])
// M, N divisible by 128; K divisible by 16.
// ---------------------------------------------------------------------------
#define HBM 128
#define HBN 128
#define HBK 16

template <bool A_KM, bool B_KN, bool HAS_BIAS>
__global__ __launch_bounds__(256) void gemm128_kernel(
    const float* __restrict__ A, const float* __restrict__ B,
    float* __restrict__ C, const float* __restrict__ bias,
    int M, int N, int K,
    long long strideA, long long strideB, long long strideC)
{
    A += (long long)blockIdx.z * strideA;
    B += (long long)blockIdx.z * strideB;
    C += (long long)blockIdx.z * strideC;

    const int bm = blockIdx.y * HBM;
    const int bn = blockIdx.x * HBN;

    __shared__ float As[HBK][HBM];
    __shared__ float Bs[HBK][HBN];

    const int tid = threadIdx.x;
    const int tx = tid & 15;   // 16 col groups
    const int ty = tid >> 4;   // 16 row groups

    float acc[8][8];
#pragma unroll
    for (int i = 0; i < 8; i++)
#pragma unroll
        for (int j = 0; j < 8; j++) acc[i][j] = 0.0f;

    for (int k0 = 0; k0 < K; k0 += HBK) {
        // ---- A tile -> As[k][m]  (128x16 = 512 float4)
        if (A_KM) {
            int f4a = tid;
            int kr = f4a >> 5, c = (f4a & 31) << 2;
            *(float4*)&As[kr][c] =
                *(const float4*)(A + (long)(k0 + kr) * M + bm + c);
            int f4b = tid + 256;
            int kr2 = f4b >> 5, c2 = (f4b & 31) << 2;
            *(float4*)&As[kr2][c2] =
                *(const float4*)(A + (long)(k0 + kr2) * M + bm + c2);
        } else {
            int m  = tid >> 2;           // 0..63
            int k4 = (tid & 3) << 2;
            float4 v = *(const float4*)(A + (long)(bm + m) * K + k0 + k4);
            As[k4 + 0][m] = v.x; As[k4 + 1][m] = v.y;
            As[k4 + 2][m] = v.z; As[k4 + 3][m] = v.w;
            int m2 = m + 64;
            float4 w = *(const float4*)(A + (long)(bm + m2) * K + k0 + k4);
            As[k4 + 0][m2] = w.x; As[k4 + 1][m2] = w.y;
            As[k4 + 2][m2] = w.z; As[k4 + 3][m2] = w.w;
        }
        // ---- B tile -> Bs[k][n]
        if (B_KN) {
            int f4a = tid;
            int kr = f4a >> 5, c = (f4a & 31) << 2;
            *(float4*)&Bs[kr][c] =
                *(const float4*)(B + (long)(k0 + kr) * N + bn + c);
            int f4b = tid + 256;
            int kr2 = f4b >> 5, c2 = (f4b & 31) << 2;
            *(float4*)&Bs[kr2][c2] =
                *(const float4*)(B + (long)(k0 + kr2) * N + bn + c2);
        } else {
            int n  = tid >> 2;           // 0..63
            int k4 = (tid & 3) << 2;
            float4 v = *(const float4*)(B + (long)(bn + n) * K + k0 + k4);
            Bs[k4 + 0][n] = v.x; Bs[k4 + 1][n] = v.y;
            Bs[k4 + 2][n] = v.z; Bs[k4 + 3][n] = v.w;
            int n2 = n + 64;
            float4 w = *(const float4*)(B + (long)(bn + n2) * K + k0 + k4);
            Bs[k4 + 0][n2] = w.x; Bs[k4 + 1][n2] = w.y;
            Bs[k4 + 2][n2] = w.z; Bs[k4 + 3][n2] = w.w;
        }
        __syncthreads();

#pragma unroll
        for (int kk = 0; kk < HBK; kk++) {
            float a[8], b[8];
            *(float4*)&a[0] = *(float4*)&As[kk][ty << 2];
            *(float4*)&a[4] = *(float4*)&As[kk][64 + (ty << 2)];
            *(float4*)&b[0] = *(float4*)&Bs[kk][tx << 2];
            *(float4*)&b[4] = *(float4*)&Bs[kk][64 + (tx << 2)];
#pragma unroll
            for (int i = 0; i < 8; i++)
#pragma unroll
                for (int j = 0; j < 8; j++) acc[i][j] += a[i] * b[j];
        }
        __syncthreads();
    }

    // ---- store: rows {ty*4+i, 64+ty*4+i}, cols {tx*4+j, 64+tx*4+j}
#pragma unroll
    for (int half = 0; half < 2; half++) {
#pragma unroll
        for (int i = 0; i < 4; i++) {
            int mi = half * 4 + i;
            int m = bm + half * 64 + (ty << 2) + i;
            float bv = HAS_BIAS ? bias[m] : 0.0f;
            long rowoff = (long)m * N;
            float4 v0, v1;
            v0.x = acc[mi][0] + bv; v0.y = acc[mi][1] + bv;
            v0.z = acc[mi][2] + bv; v0.w = acc[mi][3] + bv;
            v1.x = acc[mi][4] + bv; v1.y = acc[mi][5] + bv;
            v1.z = acc[mi][6] + bv; v1.w = acc[mi][7] + bv;
            *(float4*)(C + rowoff + bn + (tx << 2))      = v0;
            *(float4*)(C + rowoff + bn + 64 + (tx << 2)) = v1;
        }
    }
}

// ---------------------------------------------------------------------------
// Row softmax over N=4096, one block per row, row cached in smem.
// ---------------------------------------------------------------------------
__global__ __launch_bounds__(256) void softmax_kernel(float* __restrict__ S)
{
    __shared__ float row[HW];
    __shared__ float redbuf[8];
    const long base = (long)blockIdx.x * HW;
    const int tid = threadIdx.x;

    float m = -INFINITY;
    for (int i = tid; i < HW; i += 256) {
        float v = S[base + i];
        row[i] = v;
        m = fmaxf(m, v);
    }
#pragma unroll
    for (int o = 16; o; o >>= 1) m = fmaxf(m, __shfl_xor_sync(0xffffffffu, m, o));
    if ((tid & 31) == 0) redbuf[tid >> 5] = m;
    __syncthreads();
    if (tid < 32) {
        float v = (tid < 8) ? redbuf[tid] : -INFINITY;
#pragma unroll
        for (int o = 4; o; o >>= 1) v = fmaxf(v, __shfl_xor_sync(0xffffffffu, v, o));
        if (tid == 0) redbuf[0] = v;
    }
    __syncthreads();
    const float rowmax = redbuf[0];
    __syncthreads();

    float s = 0.0f;
    for (int i = tid; i < HW; i += 256) {
        float e = __expf(row[i] - rowmax);
        row[i] = e;
        s += e;
    }
#pragma unroll
    for (int o = 16; o; o >>= 1) s += __shfl_xor_sync(0xffffffffu, s, o);
    if ((tid & 31) == 0) redbuf[tid >> 5] = s;
    __syncthreads();
    if (tid < 32) {
        float v = (tid < 8) ? redbuf[tid] : 0.0f;
#pragma unroll
        for (int o = 4; o; o >>= 1) v += __shfl_xor_sync(0xffffffffu, v, o);
        if (tid == 0) redbuf[0] = v;
    }
    __syncthreads();
    const float inv = 1.0f / redbuf[0];
    for (int i = tid; i < HW; i += 256) S[base + i] = row[i] * inv;
}

// ---------------------------------------------------------------------------
// Launch
// ---------------------------------------------------------------------------
static float* sym_addr_f(const void* symbol)
{
    void* p = nullptr;
    cudaGetSymbolAddress(&p, symbol);
    return (float*)p;
}

extern "C" void kernel_launch(void* const* d_in, const int* in_sizes, int n_in,
                              void* d_out, int out_size)
{
    const float* content = (const float*)d_in[0];
    const float* style   = (const float*)d_in[1];
    const float* f_w     = (const float*)d_in[2];
    const float* f_b     = (const float*)d_in[3];
    const float* g_w     = (const float*)d_in[4];
    const float* g_b     = (const float*)d_in[5];
    const float* h_w     = (const float*)d_in[6];
    const float* h_b     = (const float*)d_in[7];
    const float* out_w   = (const float*)d_in[8];
    const float* out_b   = (const float*)d_in[9];
    float* out = (float*)d_out;

    float* xr = sym_addr_f(g_xr);
    float* f  = sym_addr_f(g_f);
    float* g  = sym_addr_f(g_g);
    float* h  = sym_addr_f(g_h);
    float* S  = sym_addr_f(g_S);
    float* o  = sym_addr_f(g_o);

    const long long sX  = (long long)CIN * HW;   // (512,4096) batch stride
    const long long sF  = (long long)C8 * HW;    // (64,4096)
    const long long sS  = (long long)HW * HW;    // (4096,4096)

    dim3 blk(256);

    // 1. resize style -> xr
    {
        long total = (long)BATCH * CIN * HW;
        resize_kernel<<<(unsigned)(total / 256), 256>>>(style, xr);
    }
    // 2. f = f_w @ content + f_b   (M=64)
    gemm64_kernel<false, true, true><<<dim3(HW / GBN, C8 / GBM, BATCH), blk>>>(
        f_w, content, f, f_b, C8, HW, CIN, 0, sX, sF);
    // 3. g = g_w @ xr + g_b        (M=64)
    gemm64_kernel<false, true, true><<<dim3(HW / GBN, C8 / GBM, BATCH), blk>>>(
        g_w, xr, g, g_b, C8, HW, CIN, 0, sX, sF);
    // 4. h = h_w @ xr + h_b        (M=512)
    gemm128_kernel<false, true, true><<<dim3(HW / HBN, CIN / HBM, BATCH), blk>>>(
        h_w, xr, h, h_b, CIN, HW, CIN, 0, sX, sX);
    // 5. S[m][n] = sum_c f[c][m] g[c][n]   (M=N=4096, K=64)
    gemm128_kernel<true, true, false><<<dim3(HW / HBN, HW / HBM, BATCH), blk>>>(
        f, g, S, nullptr, HW, HW, C8, sF, sF, sS);
    // 6. P = softmax rows
    softmax_kernel<<<BATCH * HW, 256>>>(S);
    // 7. o[c][m] = sum_n h[c][n] P[m][n]   (M=512, N=4096, K=4096)
    gemm128_kernel<false, false, false><<<dim3(HW / HBN, CIN / HBM, BATCH), blk>>>(
        h, S, o, nullptr, CIN, HW, HW, sX, sS, sX);
    // 8. out = out_w @ o + out_b   (M=512)
    gemm128_kernel<false, true, true><<<dim3(HW / HBN, CIN / HBM, BATCH), blk>>>(
        out_w, o, out, out_b, CIN, HW, CIN, 0, sX, sX);
}

// round 4
// speedup vs baseline: 1.5565x; 1.5565x over previous
#include <cuda_runtime.h>
#include <math.h>
#include <stdint.h>

// ---------------------------------------------------------------------------
// SANet attention block. tf32 tensor-core GEMMs + fused softmax-free PV.
//   f = conv1x1(content, f_w, f_b)          fp32 gemm64       (B, 64, 4096)
//   xr = bilinear_resize(style)             fp32              (B, 512, 4096)
//   g = conv1x1(xr, g_w, g_b)               fp32 gemm64       (B, 64, 4096)
//   h = conv1x1(xr, h_w, h_b)               tf32 mma          (B, 512, 4096)
//   S = f^T g                                3xtf32 mma        (B, 4096, 4096)
//   mx, Z = rowwise max / sum exp(S-mx)     rowstats
//   o = h @ softmax(S)^T                    tf32 mma, exp fused in B-load
//   out = conv1x1(o, out_w, out_b)          tf32 mma
// ---------------------------------------------------------------------------

#define BATCH 4
#define CIN   512
#define C8    64
#define HW    4096
#define SHW   6400   // 80*80

__device__ float g_xr[(size_t)BATCH * CIN * HW];
__device__ float g_f [(size_t)BATCH * C8  * HW];
__device__ float g_g [(size_t)BATCH * C8  * HW];
__device__ float g_h [(size_t)BATCH * CIN * HW];
__device__ float g_S [(size_t)BATCH * HW  * HW];   // raw logits (268 MB)
__device__ float g_o [(size_t)BATCH * CIN * HW];
__device__ float g_mx[(size_t)BATCH * HW];
__device__ float g_sz[(size_t)BATCH * HW];

// ---------------------------------------------------------------------------
__device__ __forceinline__ float tf32f(float x) {
    uint32_t u;
    asm("cvt.rna.tf32.f32 %0, %1;" : "=r"(u) : "f"(x));
    return __uint_as_float(u);
}
__device__ __forceinline__ uint32_t fasu(float x) { return __float_as_uint(x); }

#define MMA8(d, a, b)                                                        \
    asm volatile(                                                            \
        "mma.sync.aligned.m16n8k8.row.col.f32.tf32.tf32.f32 "                \
        "{%0,%1,%2,%3}, {%4,%5,%6,%7}, {%8,%9}, {%0,%1,%2,%3};"              \
        : "+f"(d[0]), "+f"(d[1]), "+f"(d[2]), "+f"(d[3])                     \
        : "r"(a[0]), "r"(a[1]), "r"(a[2]), "r"(a[3]), "r"(b[0]), "r"(b[1]))

// ---------------------------------------------------------------------------
// Bilinear resize 80x80 -> 64x64.
// ---------------------------------------------------------------------------
__global__ __launch_bounds__(256) void resize_kernel(
    const float* __restrict__ style, float* __restrict__ xr)
{
    long idx = (long)blockIdx.x * blockDim.x + threadIdx.x;
    int m      = (int)(idx & (HW - 1));
    long plane = idx >> 12;
    int x = m & 63, y = m >> 6;

    float sy = fmaxf((y + 0.5f) * 1.25f - 0.5f, 0.0f);
    int   y0 = (int)sy;
    int   y1 = min(y0 + 1, 79);
    float wy = sy - (float)y0;
    float sx = fmaxf((x + 0.5f) * 1.25f - 0.5f, 0.0f);
    int   x0 = (int)sx;
    int   x1 = min(x0 + 1, 79);
    float wx = sx - (float)x0;

    const float* p = style + plane * SHW;
    float top = p[y0 * 80 + x0] * (1.0f - wx) + p[y0 * 80 + x1] * wx;
    float bot = p[y1 * 80 + x0] * (1.0f - wx) + p[y1 * 80 + x1] * wx;
    xr[idx] = top * (1.0f - wy) + bot * wy;
}

// ---------------------------------------------------------------------------
// fp32 64x128x16 GEMM for the tiny f/g convs (A: MxK row-major, B: KxN).
// ---------------------------------------------------------------------------
#define GBM 64
#define GBN 128
#define GBK 16

__global__ __launch_bounds__(256) void gemm64_kernel(
    const float* __restrict__ A, const float* __restrict__ B,
    float* __restrict__ C, const float* __restrict__ bias,
    int M, int N, int K, long long strideB, long long strideC)
{
    B += (long long)blockIdx.z * strideB;
    C += (long long)blockIdx.z * strideC;

    const int bm = blockIdx.y * GBM;
    const int bn = blockIdx.x * GBN;

    __shared__ float As[GBK][GBM];
    __shared__ float Bs[GBK][GBN];

    const int tid = threadIdx.x;
    const int tx = tid & 15;
    const int ty = tid >> 4;

    float acc[4][8];
#pragma unroll
    for (int i = 0; i < 4; i++)
#pragma unroll
        for (int j = 0; j < 8; j++) acc[i][j] = 0.0f;

    for (int k0 = 0; k0 < K; k0 += GBK) {
        {
            int m  = tid >> 2;
            int k4 = (tid & 3) << 2;
            float4 v = *(const float4*)(A + (long)(bm + m) * K + k0 + k4);
            As[k4 + 0][m] = v.x; As[k4 + 1][m] = v.y;
            As[k4 + 2][m] = v.z; As[k4 + 3][m] = v.w;
        }
        {
            int f4 = tid * 2;
            int kr0 = f4 >> 5, c0 = (f4 & 31) << 2;
            *(float4*)&Bs[kr0][c0] =
                *(const float4*)(B + (long)(k0 + kr0) * N + bn + c0);
            int f41 = f4 + 1;
            int kr1 = f41 >> 5, c1 = (f41 & 31) << 2;
            *(float4*)&Bs[kr1][c1] =
                *(const float4*)(B + (long)(k0 + kr1) * N + bn + c1);
        }
        __syncthreads();

#pragma unroll
        for (int kk = 0; kk < GBK; kk++) {
            float a[4], b[8];
            *(float4*)a     = *(float4*)&As[kk][ty << 2];
            *(float4*)&b[0] = *(float4*)&Bs[kk][tx << 2];
            *(float4*)&b[4] = *(float4*)&Bs[kk][64 + (tx << 2)];
#pragma unroll
            for (int i = 0; i < 4; i++)
#pragma unroll
                for (int j = 0; j < 8; j++) acc[i][j] += a[i] * b[j];
        }
        __syncthreads();
    }

#pragma unroll
    for (int i = 0; i < 4; i++) {
        int m = bm + (ty << 2) + i;
        float bv = bias[m];
        long rowoff = (long)m * N;
        float4 v0, v1;
        v0.x = acc[i][0] + bv; v0.y = acc[i][1] + bv;
        v0.z = acc[i][2] + bv; v0.w = acc[i][3] + bv;
        v1.x = acc[i][4] + bv; v1.y = acc[i][5] + bv;
        v1.z = acc[i][6] + bv; v1.w = acc[i][7] + bv;
        *(float4*)(C + rowoff + bn + (tx << 2))      = v0;
        *(float4*)(C + rowoff + bn + 64 + (tx << 2)) = v1;
    }
}

// ---------------------------------------------------------------------------
// tf32 MMA GEMM, 128x128x32 block tile, 8 warps (4x2), warp tile 32x64.
// A: [M][K] row-major fp32 (lda = K), converted to tf32 at smem store.
// MODE 0: B = [K][N] fp32, ldb = N. Epilogue adds bias[row].
// MODE 1 (PV): B element (k,n) = exp(S[n][k] - mx[n]); ldb = K (S row = K).
//              Epilogue scales column n by 1/Z[n]. No bias.
// ---------------------------------------------------------------------------
#define TBM 128
#define TBN 128
#define TBK 32
#define SAK 36    // As row stride  (conflict-free)
#define SBN 136   // Bs row stride, direct mode
#define SBT 36    // Bs row stride, transposed mode

template <int MODE, bool BIAS>
__global__ __launch_bounds__(256, 2) void mma_gemm(
    const float* __restrict__ A, const float* __restrict__ B,
    float* __restrict__ C, const float* __restrict__ bias,
    const float* __restrict__ mx, const float* __restrict__ sz,
    int M, int N, int K,
    long long sA, long long sB, long long sC)
{
    const int z = blockIdx.z;
    A += (long long)z * sA;
    B += (long long)z * sB;
    C += (long long)z * sC;

    const int bm = blockIdx.x * TBM;
    const int bn = blockIdx.y * TBN;

    __shared__ float AsF[TBM * SAK];   // 18 KB
    __shared__ float BsF[TBN * SBT];   // 18 KB (also fits 32*136 direct mode)
    __shared__ float s_mx[TBN];
    __shared__ float s_invz[TBN];

    const int tid  = threadIdx.x;
    const int lane = tid & 31, warp = tid >> 5;
    const int gq = lane >> 2, t4 = lane & 3;
    const int wm = (warp >> 1) * 32;
    const int wn = (warp & 1) * 64;

    if (MODE == 1) {
        if (tid < TBN) {
            int idx = z * HW + bn + tid;
            s_mx[tid]   = mx[idx];
            s_invz[tid] = 1.0f / sz[idx];
        }
        __syncthreads();
    }

    float acc[2][8][4];
#pragma unroll
    for (int mi = 0; mi < 2; mi++)
#pragma unroll
        for (int nj = 0; nj < 8; nj++)
#pragma unroll
            for (int c = 0; c < 4; c++) acc[mi][nj][c] = 0.0f;

    for (int k0 = 0; k0 < K; k0 += TBK) {
        // ---- A tile (row-major [m][k])
        {
            int k4   = (tid & 7) << 2;
            int mrow = tid >> 3;
#pragma unroll
            for (int j = 0; j < 4; j++) {
                int m = mrow + 32 * j;
                float4 v = *(const float4*)(A + (long)(bm + m) * K + k0 + k4);
                float4 w;
                w.x = tf32f(v.x); w.y = tf32f(v.y);
                w.z = tf32f(v.z); w.w = tf32f(v.w);
                *(float4*)&AsF[m * SAK + k4] = w;
            }
        }
        // ---- B tile
        if (MODE == 0) {
            int n4 = (tid & 31) << 2;
            int kr = tid >> 5;
#pragma unroll
            for (int j = 0; j < 4; j++) {
                int k = kr + 8 * j;
                float4 v = *(const float4*)(B + (long)(k0 + k) * N + bn + n4);
                float4 w;
                w.x = tf32f(v.x); w.y = tf32f(v.y);
                w.z = tf32f(v.z); w.w = tf32f(v.w);
                *(float4*)&BsF[k * SBN + n4] = w;
            }
        } else {
            int kk = tid & 31;
            int nr = tid >> 5;
#pragma unroll
            for (int j = 0; j < 16; j++) {
                int n = nr + 8 * j;
                float sv = B[(long)(bn + n) * K + k0 + kk];
                float e  = __expf(sv - s_mx[n]);
                BsF[n * SBT + kk] = tf32f(e);
            }
        }
        __syncthreads();

#pragma unroll
        for (int kk = 0; kk < 4; kk++) {
            uint32_t a[2][4];
#pragma unroll
            for (int mi = 0; mi < 2; mi++) {
                const float* ap = &AsF[(wm + mi * 16 + gq) * SAK + kk * 8 + t4];
                a[mi][0] = fasu(ap[0]);
                a[mi][1] = fasu(ap[8 * SAK]);
                a[mi][2] = fasu(ap[4]);
                a[mi][3] = fasu(ap[8 * SAK + 4]);
            }
#pragma unroll
            for (int nj = 0; nj < 8; nj++) {
                uint32_t b[2];
                if (MODE == 0) {
                    const float* bp = &BsF[(kk * 8 + t4) * SBN + wn + nj * 8 + gq];
                    b[0] = fasu(bp[0]);
                    b[1] = fasu(bp[4 * SBN]);
                } else {
                    const float* bp = &BsF[(wn + nj * 8 + gq) * SBT + kk * 8 + t4];
                    b[0] = fasu(bp[0]);
                    b[1] = fasu(bp[4]);
                }
                MMA8(acc[0][nj], a[0], b);
                MMA8(acc[1][nj], a[1], b);
            }
        }
        __syncthreads();
    }

    // ---- epilogue
#pragma unroll
    for (int mi = 0; mi < 2; mi++) {
        int r0 = bm + wm + mi * 16 + gq;
        float bv0 = BIAS ? bias[r0] : 0.0f;
        float bv8 = BIAS ? bias[r0 + 8] : 0.0f;
#pragma unroll
        for (int nj = 0; nj < 8; nj++) {
            int cl = wn + nj * 8 + 2 * t4;
            float x0 = acc[mi][nj][0], x1 = acc[mi][nj][1];
            float x2 = acc[mi][nj][2], x3 = acc[mi][nj][3];
            if (MODE == 1) {
                float z0 = s_invz[cl], z1 = s_invz[cl + 1];
                x0 *= z0; x1 *= z1; x2 *= z0; x3 *= z1;
            } else {
                x0 += bv0; x1 += bv0; x2 += bv8; x3 += bv8;
            }
            float2 p0, p1;
            p0.x = x0; p0.y = x1; p1.x = x2; p1.y = x3;
            *(float2*)(C + (long)r0 * N + bn + cl)       = p0;
            *(float2*)(C + (long)(r0 + 8) * N + bn + cl) = p1;
        }
    }
}

// ---------------------------------------------------------------------------
// S = f^T g in 3xtf32 (hi/lo split): near-fp32 accuracy on tensor cores.
// A = f [K=64][M] (lda = HW), B = g [K=64][N] (ldb = HW). BK = 16.
// ---------------------------------------------------------------------------
#define SK_BK 16
#define SK_SA 20
#define SK_SB 136

__global__ __launch_bounds__(256, 2) void s_gemm3_kernel(
    const float* __restrict__ Af, const float* __restrict__ Bg,
    float* __restrict__ C,
    long long sA, long long sB, long long sC)
{
    const int z = blockIdx.z;
    Af += (long long)z * sA;
    Bg += (long long)z * sB;
    C  += (long long)z * sC;

    const int bm = blockIdx.x * TBM;
    const int bn = blockIdx.y * TBN;

    __shared__ float AsH[TBM * SK_SA];     // 10 KB
    __shared__ float AsL[TBM * SK_SA];     // 10 KB
    __shared__ float BsH[SK_BK * SK_SB];   // 8.7 KB
    __shared__ float BsL[SK_BK * SK_SB];   // 8.7 KB

    const int tid  = threadIdx.x;
    const int lane = tid & 31, warp = tid >> 5;
    const int gq = lane >> 2, t4 = lane & 3;
    const int wm = (warp >> 1) * 32;
    const int wn = (warp & 1) * 64;

    float acc[2][8][4];
#pragma unroll
    for (int mi = 0; mi < 2; mi++)
#pragma unroll
        for (int nj = 0; nj < 8; nj++)
#pragma unroll
            for (int c = 0; c < 4; c++) acc[mi][nj][c] = 0.0f;

    for (int k0 = 0; k0 < C8; k0 += SK_BK) {
        // ---- A tile: transpose [k][m] -> AsH/AsL [m][k]
        {
            int k  = tid >> 4;               // 0..15
            int m4b = (tid & 15) << 2;       // 0..60
#pragma unroll
            for (int j = 0; j < 2; j++) {
                int m4 = m4b + 64 * j;
                float4 v = *(const float4*)(Af + (long)(k0 + k) * HW + bm + m4);
                float vv[4] = {v.x, v.y, v.z, v.w};
#pragma unroll
                for (int i = 0; i < 4; i++) {
                    float hi = tf32f(vv[i]);
                    float lo = tf32f(vv[i] - hi);
                    AsH[(m4 + i) * SK_SA + k] = hi;
                    AsL[(m4 + i) * SK_SA + k] = lo;
                }
            }
        }
        // ---- B tile: direct [k][n]
        {
            int kr = tid >> 5;               // 0..7
            int n4 = (tid & 31) << 2;
#pragma unroll
            for (int j = 0; j < 2; j++) {
                int k = kr + 8 * j;
                float4 v = *(const float4*)(Bg + (long)(k0 + k) * HW + bn + n4);
                float vv[4] = {v.x, v.y, v.z, v.w};
#pragma unroll
                for (int i = 0; i < 4; i++) {
                    float hi = tf32f(vv[i]);
                    float lo = tf32f(vv[i] - hi);
                    BsH[k * SK_SB + n4 + i] = hi;
                    BsL[k * SK_SB + n4 + i] = lo;
                }
            }
        }
        __syncthreads();

#pragma unroll
        for (int kk = 0; kk < 2; kk++) {
            uint32_t aH[2][4], aL[2][4];
#pragma unroll
            for (int mi = 0; mi < 2; mi++) {
                const float* ah = &AsH[(wm + mi * 16 + gq) * SK_SA + kk * 8 + t4];
                const float* al = &AsL[(wm + mi * 16 + gq) * SK_SA + kk * 8 + t4];
                aH[mi][0] = fasu(ah[0]);
                aH[mi][1] = fasu(ah[8 * SK_SA]);
                aH[mi][2] = fasu(ah[4]);
                aH[mi][3] = fasu(ah[8 * SK_SA + 4]);
                aL[mi][0] = fasu(al[0]);
                aL[mi][1] = fasu(al[8 * SK_SA]);
                aL[mi][2] = fasu(al[4]);
                aL[mi][3] = fasu(al[8 * SK_SA + 4]);
            }
#pragma unroll
            for (int nj = 0; nj < 8; nj++) {
                const float* bh = &BsH[(kk * 8 + t4) * SK_SB + wn + nj * 8 + gq];
                const float* bl = &BsL[(kk * 8 + t4) * SK_SB + wn + nj * 8 + gq];
                uint32_t bH[2], bL[2];
                bH[0] = fasu(bh[0]); bH[1] = fasu(bh[4 * SK_SB]);
                bL[0] = fasu(bl[0]); bL[1] = fasu(bl[4 * SK_SB]);
#pragma unroll
                for (int mi = 0; mi < 2; mi++) {
                    MMA8(acc[mi][nj], aH[mi], bH);   // hi*hi
                    MMA8(acc[mi][nj], aH[mi], bL);   // hi*lo
                    MMA8(acc[mi][nj], aL[mi], bH);   // lo*hi
                }
            }
        }
        __syncthreads();
    }

#pragma unroll
    for (int mi = 0; mi < 2; mi++) {
        int r0 = bm + wm + mi * 16 + gq;
#pragma unroll
        for (int nj = 0; nj < 8; nj++) {
            int cl = wn + nj * 8 + 2 * t4;
            float2 p0, p1;
            p0.x = acc[mi][nj][0]; p0.y = acc[mi][nj][1];
            p1.x = acc[mi][nj][2]; p1.y = acc[mi][nj][3];
            *(float2*)(C + (long)r0 * HW + bn + cl)       = p0;
            *(float2*)(C + (long)(r0 + 8) * HW + bn + cl) = p1;
        }
    }
}

// ---------------------------------------------------------------------------
// Per-row max + sum(exp(v - max)) over N=4096. One block per row.
// ---------------------------------------------------------------------------
__global__ __launch_bounds__(256) void rowstats_kernel(
    const float* __restrict__ S, float* __restrict__ mx, float* __restrict__ sz)
{
    __shared__ float row[HW];
    __shared__ float redbuf[8];
    const long base = (long)blockIdx.x * HW;
    const int tid = threadIdx.x;

    float m = -INFINITY;
    for (int i = tid; i < HW; i += 256) {
        float v = S[base + i];
        row[i] = v;
        m = fmaxf(m, v);
    }
#pragma unroll
    for (int o = 16; o; o >>= 1) m = fmaxf(m, __shfl_xor_sync(0xffffffffu, m, o));
    if ((tid & 31) == 0) redbuf[tid >> 5] = m;
    __syncthreads();
    if (tid < 32) {
        float v = (tid < 8) ? redbuf[tid] : -INFINITY;
#pragma unroll
        for (int o = 4; o; o >>= 1) v = fmaxf(v, __shfl_xor_sync(0xffffffffu, v, o));
        if (tid == 0) redbuf[0] = v;
    }
    __syncthreads();
    const float rowmax = redbuf[0];
    __syncthreads();

    float s = 0.0f;
    for (int i = tid; i < HW; i += 256) s += __expf(row[i] - rowmax);
#pragma unroll
    for (int o = 16; o; o >>= 1) s += __shfl_xor_sync(0xffffffffu, s, o);
    if ((tid & 31) == 0) redbuf[tid >> 5] = s;
    __syncthreads();
    if (tid < 32) {
        float v = (tid < 8) ? redbuf[tid] : 0.0f;
#pragma unroll
        for (int o = 4; o; o >>= 1) v += __shfl_xor_sync(0xffffffffu, v, o);
        if (tid == 0) {
            mx[blockIdx.x] = rowmax;
            sz[blockIdx.x] = v;
        }
    }
}

// ---------------------------------------------------------------------------
static float* sym_addr_f(const void* symbol)
{
    void* p = nullptr;
    cudaGetSymbolAddress(&p, symbol);
    return (float*)p;
}

extern "C" void kernel_launch(void* const* d_in, const int* in_sizes, int n_in,
                              void* d_out, int out_size)
{
    const float* content = (const float*)d_in[0];
    const float* style   = (const float*)d_in[1];
    const float* f_w     = (const float*)d_in[2];
    const float* f_b     = (const float*)d_in[3];
    const float* g_w     = (const float*)d_in[4];
    const float* g_b     = (const float*)d_in[5];
    const float* h_w     = (const float*)d_in[6];
    const float* h_b     = (const float*)d_in[7];
    const float* out_w   = (const float*)d_in[8];
    const float* out_b   = (const float*)d_in[9];
    float* out = (float*)d_out;

    float* xr = sym_addr_f(g_xr);
    float* f  = sym_addr_f(g_f);
    float* g  = sym_addr_f(g_g);
    float* h  = sym_addr_f(g_h);
    float* S  = sym_addr_f(g_S);
    float* o  = sym_addr_f(g_o);
    float* mx = sym_addr_f(g_mx);
    float* sz = sym_addr_f(g_sz);

    const long long sX = (long long)CIN * HW;
    const long long sF = (long long)C8 * HW;
    const long long sS = (long long)HW * HW;

    // 1. resize style -> xr
    {
        long total = (long)BATCH * CIN * HW;
        resize_kernel<<<(unsigned)(total / 256), 256>>>(style, xr);
    }
    // 2/3. f, g convs (fp32, tiny)
    gemm64_kernel<<<dim3(HW / GBN, C8 / GBM, BATCH), 256>>>(
        f_w, content, f, f_b, C8, HW, CIN, sX, sF);
    gemm64_kernel<<<dim3(HW / GBN, C8 / GBM, BATCH), 256>>>(
        g_w, xr, g, g_b, C8, HW, CIN, sX, sF);
    // 4. h = h_w @ xr + h_b (tf32)
    mma_gemm<0, true><<<dim3(CIN / TBM, HW / TBN, BATCH), 256>>>(
        h_w, xr, h, h_b, nullptr, nullptr, CIN, HW, CIN, 0, sX, sX);
    // 5. S = f^T g (3xtf32)
    s_gemm3_kernel<<<dim3(HW / TBM, HW / TBN, BATCH), 256>>>(
        f, g, S, sF, sF, sS);
    // 6. row stats (max, sumexp)
    rowstats_kernel<<<BATCH * HW, 256>>>(S, mx, sz);
    // 7. o = h @ softmax(S)^T (tf32, exp fused into B load, 1/Z in epilogue)
    mma_gemm<1, false><<<dim3(CIN / TBM, HW / TBN, BATCH), 256>>>(
        h, S, o, nullptr, mx, sz, CIN, HW, HW, sX, sS, sX);
    // 8. out = out_w @ o + out_b (tf32)
    mma_gemm<0, true><<<dim3(CIN / TBM, HW / TBN, BATCH), 256>>>(
        out_w, o, out, out_b, nullptr, nullptr, CIN, HW, CIN, 0, sX, sX);
}

// round 5
// speedup vs baseline: 2.0441x; 1.3133x over previous
#include <cuda_runtime.h>
#include <math.h>
#include <stdint.h>

// ---------------------------------------------------------------------------
// SANet attention block. tf32 tensor-core GEMMs, cp.async pipelined.
//   f  = conv1x1(content)            fp32 gemm64
//   xr = bilinear_resize(style)      fp32 (+ tf32-rounded copy xr32)
//   g  = conv1x1(xr)                 fp32 gemm64
//   h  = conv1x1(xr32)               tf32 mma-pipe  (epilogue rounds -> h32)
//   S  = f^T g                       3xtf32 mma (hi/lo split)
//   P  = softmax(S) rows             rowstats, written back tf32-rounded
//   o  = h32 @ P^T                   tf32 mma-pipe, transposed B (-> o32)
//   out= conv1x1(o32)                tf32 mma-pipe
// ---------------------------------------------------------------------------

#define BATCH 4
#define CIN   512
#define C8    64
#define HW    4096
#define SHW   6400   // 80*80

__device__ float g_xr  [(size_t)BATCH * CIN * HW];
__device__ float g_xr32[(size_t)BATCH * CIN * HW];
__device__ float g_f   [(size_t)BATCH * C8  * HW];
__device__ float g_g   [(size_t)BATCH * C8  * HW];
__device__ float g_h32 [(size_t)BATCH * CIN * HW];
__device__ float g_S   [(size_t)BATCH * HW  * HW];   // logits, then P~ (268 MB)
__device__ float g_o32 [(size_t)BATCH * CIN * HW];
__device__ float g_hw32[CIN * CIN];
__device__ float g_ow32[CIN * CIN];

// ---------------------------------------------------------------------------
__device__ __forceinline__ float tf32f(float x) {
    uint32_t u;
    asm("cvt.rna.tf32.f32 %0, %1;" : "=r"(u) : "f"(x));
    return __uint_as_float(u);
}
__device__ __forceinline__ uint32_t fasu(float x) { return __float_as_uint(x); }

#define MMA8(d, a, b)                                                        \
    asm volatile(                                                            \
        "mma.sync.aligned.m16n8k8.row.col.f32.tf32.tf32.f32 "                \
        "{%0,%1,%2,%3}, {%4,%5,%6,%7}, {%8,%9}, {%0,%1,%2,%3};"              \
        : "+f"(d[0]), "+f"(d[1]), "+f"(d[2]), "+f"(d[3])                     \
        : "r"(a[0]), "r"(a[1]), "r"(a[2]), "r"(a[3]), "r"(b[0]), "r"(b[1]))

__device__ __forceinline__ void cpa16(uint32_t dst, const void* src) {
    asm volatile("cp.async.ca.shared.global [%0], [%1], 16;\n"
                 :: "r"(dst), "l"(src));
}
#define CP_COMMIT() asm volatile("cp.async.commit_group;\n" ::: "memory")
#define CP_WAIT1()  asm volatile("cp.async.wait_group 1;\n" ::: "memory")

// ---------------------------------------------------------------------------
// Bilinear resize 80x80 -> 64x64; writes fp32 and tf32-rounded copies.
// ---------------------------------------------------------------------------
__global__ __launch_bounds__(256) void resize_kernel(
    const float* __restrict__ style, float* __restrict__ xr,
    float* __restrict__ xr32)
{
    long idx = (long)blockIdx.x * blockDim.x + threadIdx.x;
    int m      = (int)(idx & (HW - 1));
    long plane = idx >> 12;
    int x = m & 63, y = m >> 6;

    float sy = fmaxf((y + 0.5f) * 1.25f - 0.5f, 0.0f);
    int   y0 = (int)sy;
    int   y1 = min(y0 + 1, 79);
    float wy = sy - (float)y0;
    float sx = fmaxf((x + 0.5f) * 1.25f - 0.5f, 0.0f);
    int   x0 = (int)sx;
    int   x1 = min(x0 + 1, 79);
    float wx = sx - (float)x0;

    const float* p = style + plane * SHW;
    float top = p[y0 * 80 + x0] * (1.0f - wx) + p[y0 * 80 + x1] * wx;
    float bot = p[y1 * 80 + x0] * (1.0f - wx) + p[y1 * 80 + x1] * wx;
    float v = top * (1.0f - wy) + bot * wy;
    xr[idx]   = v;
    xr32[idx] = tf32f(v);
}

// Round an array to tf32 (for weights).
__global__ __launch_bounds__(256) void round_kernel(
    const float* __restrict__ src, float* __restrict__ dst, int n)
{
    int i = blockIdx.x * 256 + threadIdx.x;
    if (i < n) dst[i] = tf32f(src[i]);
}

// ---------------------------------------------------------------------------
// fp32 64x128x16 GEMM for the tiny f/g convs (A: MxK row-major, B: KxN).
// ---------------------------------------------------------------------------
#define GBM 64
#define GBN 128
#define GBK 16

__global__ __launch_bounds__(256) void gemm64_kernel(
    const float* __restrict__ A, const float* __restrict__ B,
    float* __restrict__ C, const float* __restrict__ bias,
    int M, int N, int K, long long strideB, long long strideC)
{
    B += (long long)blockIdx.z * strideB;
    C += (long long)blockIdx.z * strideC;

    const int bm = blockIdx.y * GBM;
    const int bn = blockIdx.x * GBN;

    __shared__ float As[GBK][GBM];
    __shared__ float Bs[GBK][GBN];

    const int tid = threadIdx.x;
    const int tx = tid & 15;
    const int ty = tid >> 4;

    float acc[4][8];
#pragma unroll
    for (int i = 0; i < 4; i++)
#pragma unroll
        for (int j = 0; j < 8; j++) acc[i][j] = 0.0f;

    for (int k0 = 0; k0 < K; k0 += GBK) {
        {
            int m  = tid >> 2;
            int k4 = (tid & 3) << 2;
            float4 v = *(const float4*)(A + (long)(bm + m) * K + k0 + k4);
            As[k4 + 0][m] = v.x; As[k4 + 1][m] = v.y;
            As[k4 + 2][m] = v.z; As[k4 + 3][m] = v.w;
        }
        {
            int f4 = tid * 2;
            int kr0 = f4 >> 5, c0 = (f4 & 31) << 2;
            *(float4*)&Bs[kr0][c0] =
                *(const float4*)(B + (long)(k0 + kr0) * N + bn + c0);
            int f41 = f4 + 1;
            int kr1 = f41 >> 5, c1 = (f41 & 31) << 2;
            *(float4*)&Bs[kr1][c1] =
                *(const float4*)(B + (long)(k0 + kr1) * N + bn + c1);
        }
        __syncthreads();

#pragma unroll
        for (int kk = 0; kk < GBK; kk++) {
            float a[4], b[8];
            *(float4*)a     = *(float4*)&As[kk][ty << 2];
            *(float4*)&b[0] = *(float4*)&Bs[kk][tx << 2];
            *(float4*)&b[4] = *(float4*)&Bs[kk][64 + (tx << 2)];
#pragma unroll
            for (int i = 0; i < 4; i++)
#pragma unroll
                for (int j = 0; j < 8; j++) acc[i][j] += a[i] * b[j];
        }
        __syncthreads();
    }

#pragma unroll
    for (int i = 0; i < 4; i++) {
        int m = bm + (ty << 2) + i;
        float bv = bias[m];
        long rowoff = (long)m * N;
        float4 v0, v1;
        v0.x = acc[i][0] + bv; v0.y = acc[i][1] + bv;
        v0.z = acc[i][2] + bv; v0.w = acc[i][3] + bv;
        v1.x = acc[i][4] + bv; v1.y = acc[i][5] + bv;
        v1.z = acc[i][6] + bv; v1.w = acc[i][7] + bv;
        *(float4*)(C + rowoff + bn + (tx << 2))      = v0;
        *(float4*)(C + rowoff + bn + 64 + (tx << 2)) = v1;
    }
}

// ---------------------------------------------------------------------------
// Pipelined tf32 MMA GEMM. 128x128 tile, TBK=16, 2-stage cp.async.
// A: [M][K] row-major, pre-rounded to tf32.
// TRANSB=0: B = [K][N] pre-rounded tf32.   TRANSB=1: B = [N][K] (PV: P~).
// BIAS: add bias[row]. ROUND: round outputs to tf32 before store.
// ---------------------------------------------------------------------------
#define TBM 128
#define TBN 128
#define TBK 16
#define SAK 20    // As row stride (floats); conflict-free fragment banks
#define SBN 136   // Bs row stride, direct
#define SBT 20    // Bs row stride, transposed

template <bool TRANSB, bool BIAS, bool ROUND>
__global__ __launch_bounds__(256, 2) void mma_pipe(
    const float* __restrict__ A, const float* __restrict__ B,
    float* __restrict__ C, const float* __restrict__ bias,
    int M, int N, int K,
    long long sA, long long sB, long long sC)
{
    constexpr int SB_ELE = TRANSB ? (TBN * SBT) : (TBK * SBN);

    const int z = blockIdx.z;
    A += (long long)z * sA;
    B += (long long)z * sB;
    C += (long long)z * sC;

    const int bm = blockIdx.x * TBM;
    const int bn = blockIdx.y * TBN;

    __shared__ float As[2][TBM * SAK];   // 2 x 10,240 B
    __shared__ float Bs[2][SB_ELE];      // 2 x <=10,240 B

    const int tid  = threadIdx.x;
    const int lane = tid & 31, warp = tid >> 5;
    const int gq = lane >> 2, t4 = lane & 3;
    const int wm = (warp >> 1) * 32;
    const int wn = (warp & 1) * 64;

    uint32_t asb[2], bsb[2];
    asb[0] = (uint32_t)__cvta_generic_to_shared(&As[0][0]);
    asb[1] = (uint32_t)__cvta_generic_to_shared(&As[1][0]);
    bsb[0] = (uint32_t)__cvta_generic_to_shared(&Bs[0][0]);
    bsb[1] = (uint32_t)__cvta_generic_to_shared(&Bs[1][0]);

    auto issue_tile = [&](int st, int k0) {
        if (k0 < K) {
            // A tile: 128x16 = 512 float4, 2 per thread
#pragma unroll
            for (int j = 0; j < 2; j++) {
                int idx = tid + 256 * j;
                int m = idx >> 2, k4 = (idx & 3) << 2;
                cpa16(asb[st] + (uint32_t)(m * SAK + k4) * 4,
                      A + (long)(bm + m) * K + k0 + k4);
            }
            if (TRANSB) {
                // B tile: 128 rows (n) x 16 k
#pragma unroll
                for (int j = 0; j < 2; j++) {
                    int idx = tid + 256 * j;
                    int n = idx >> 2, k4 = (idx & 3) << 2;
                    cpa16(bsb[st] + (uint32_t)(n * SBT + k4) * 4,
                          B + (long)(bn + n) * K + k0 + k4);
                }
            } else {
                // B tile: 16 rows (k) x 128 n
#pragma unroll
                for (int j = 0; j < 2; j++) {
                    int idx = tid + 256 * j;
                    int k = idx >> 5, n4 = (idx & 31) << 2;
                    cpa16(bsb[st] + (uint32_t)(k * SBN + n4) * 4,
                          B + (long)(k0 + k) * N + bn + n4);
                }
            }
        }
        CP_COMMIT();
    };

    float acc[2][8][4];
#pragma unroll
    for (int mi = 0; mi < 2; mi++)
#pragma unroll
        for (int nj = 0; nj < 8; nj++)
#pragma unroll
            for (int c = 0; c < 4; c++) acc[mi][nj][c] = 0.0f;

    const int niter = K / TBK;
    issue_tile(0, 0);
    issue_tile(1, TBK);

    for (int i = 0; i < niter; i++) {
        const int st = i & 1;
        CP_WAIT1();          // oldest group (stage st) complete
        __syncthreads();     // visible to all warps

#pragma unroll
        for (int kk = 0; kk < 2; kk++) {
            uint32_t a[2][4];
#pragma unroll
            for (int mi = 0; mi < 2; mi++) {
                const float* ap = &As[st][(wm + mi * 16 + gq) * SAK + kk * 8 + t4];
                a[mi][0] = fasu(ap[0]);
                a[mi][1] = fasu(ap[8 * SAK]);
                a[mi][2] = fasu(ap[4]);
                a[mi][3] = fasu(ap[8 * SAK + 4]);
            }
#pragma unroll
            for (int nj = 0; nj < 8; nj++) {
                uint32_t b[2];
                if (TRANSB) {
                    const float* bp = &Bs[st][(wn + nj * 8 + gq) * SBT + kk * 8 + t4];
                    b[0] = fasu(bp[0]);
                    b[1] = fasu(bp[4]);
                } else {
                    const float* bp = &Bs[st][(kk * 8 + t4) * SBN + wn + nj * 8 + gq];
                    b[0] = fasu(bp[0]);
                    b[1] = fasu(bp[4 * SBN]);
                }
                MMA8(acc[0][nj], a[0], b);
                MMA8(acc[1][nj], a[1], b);
            }
        }
        __syncthreads();     // all warps done reading stage st
        issue_tile(st, (i + 2) * TBK);
    }

    // ---- epilogue
#pragma unroll
    for (int mi = 0; mi < 2; mi++) {
        int r0 = bm + wm + mi * 16 + gq;
        float bv0 = BIAS ? bias[r0] : 0.0f;
        float bv8 = BIAS ? bias[r0 + 8] : 0.0f;
#pragma unroll
        for (int nj = 0; nj < 8; nj++) {
            int cl = wn + nj * 8 + 2 * t4;
            float x0 = acc[mi][nj][0], x1 = acc[mi][nj][1];
            float x2 = acc[mi][nj][2], x3 = acc[mi][nj][3];
            if (BIAS) { x0 += bv0; x1 += bv0; x2 += bv8; x3 += bv8; }
            if (ROUND) {
                x0 = tf32f(x0); x1 = tf32f(x1);
                x2 = tf32f(x2); x3 = tf32f(x3);
            }
            float2 p0, p1;
            p0.x = x0; p0.y = x1; p1.x = x2; p1.y = x3;
            *(float2*)(C + (long)r0 * N + bn + cl)       = p0;
            *(float2*)(C + (long)(r0 + 8) * N + bn + cl) = p1;
        }
    }
}

// ---------------------------------------------------------------------------
// S = f^T g in 3xtf32 (hi/lo split).  A = f [K=64][M], B = g [K=64][N].
// ---------------------------------------------------------------------------
#define SK_BK 16
#define SK_SA 20
#define SK_SB 136

__global__ __launch_bounds__(256, 2) void s_gemm3_kernel(
    const float* __restrict__ Af, const float* __restrict__ Bg,
    float* __restrict__ C,
    long long sA, long long sB, long long sC)
{
    const int z = blockIdx.z;
    Af += (long long)z * sA;
    Bg += (long long)z * sB;
    C  += (long long)z * sC;

    const int bm = blockIdx.x * TBM;
    const int bn = blockIdx.y * TBN;

    __shared__ float AsH[TBM * SK_SA];
    __shared__ float AsL[TBM * SK_SA];
    __shared__ float BsH[SK_BK * SK_SB];
    __shared__ float BsL[SK_BK * SK_SB];

    const int tid  = threadIdx.x;
    const int lane = tid & 31, warp = tid >> 5;
    const int gq = lane >> 2, t4 = lane & 3;
    const int wm = (warp >> 1) * 32;
    const int wn = (warp & 1) * 64;

    float acc[2][8][4];
#pragma unroll
    for (int mi = 0; mi < 2; mi++)
#pragma unroll
        for (int nj = 0; nj < 8; nj++)
#pragma unroll
            for (int c = 0; c < 4; c++) acc[mi][nj][c] = 0.0f;

    for (int k0 = 0; k0 < C8; k0 += SK_BK) {
        {
            int k  = tid >> 4;
            int m4b = (tid & 15) << 2;
#pragma unroll
            for (int j = 0; j < 2; j++) {
                int m4 = m4b + 64 * j;
                float4 v = *(const float4*)(Af + (long)(k0 + k) * HW + bm + m4);
                float vv[4] = {v.x, v.y, v.z, v.w};
#pragma unroll
                for (int i = 0; i < 4; i++) {
                    float hi = tf32f(vv[i]);
                    float lo = tf32f(vv[i] - hi);
                    AsH[(m4 + i) * SK_SA + k] = hi;
                    AsL[(m4 + i) * SK_SA + k] = lo;
                }
            }
        }
        {
            int kr = tid >> 5;
            int n4 = (tid & 31) << 2;
#pragma unroll
            for (int j = 0; j < 2; j++) {
                int k = kr + 8 * j;
                float4 v = *(const float4*)(Bg + (long)(k0 + k) * HW + bn + n4);
                float vv[4] = {v.x, v.y, v.z, v.w};
#pragma unroll
                for (int i = 0; i < 4; i++) {
                    float hi = tf32f(vv[i]);
                    float lo = tf32f(vv[i] - hi);
                    BsH[k * SK_SB + n4 + i] = hi;
                    BsL[k * SK_SB + n4 + i] = lo;
                }
            }
        }
        __syncthreads();

#pragma unroll
        for (int kk = 0; kk < 2; kk++) {
            uint32_t aH[2][4], aL[2][4];
#pragma unroll
            for (int mi = 0; mi < 2; mi++) {
                const float* ah = &AsH[(wm + mi * 16 + gq) * SK_SA + kk * 8 + t4];
                const float* al = &AsL[(wm + mi * 16 + gq) * SK_SA + kk * 8 + t4];
                aH[mi][0] = fasu(ah[0]);
                aH[mi][1] = fasu(ah[8 * SK_SA]);
                aH[mi][2] = fasu(ah[4]);
                aH[mi][3] = fasu(ah[8 * SK_SA + 4]);
                aL[mi][0] = fasu(al[0]);
                aL[mi][1] = fasu(al[8 * SK_SA]);
                aL[mi][2] = fasu(al[4]);
                aL[mi][3] = fasu(al[8 * SK_SA + 4]);
            }
#pragma unroll
            for (int nj = 0; nj < 8; nj++) {
                const float* bh = &BsH[(kk * 8 + t4) * SK_SB + wn + nj * 8 + gq];
                const float* bl = &BsL[(kk * 8 + t4) * SK_SB + wn + nj * 8 + gq];
                uint32_t bH[2], bL[2];
                bH[0] = fasu(bh[0]); bH[1] = fasu(bh[4 * SK_SB]);
                bL[0] = fasu(bl[0]); bL[1] = fasu(bl[4 * SK_SB]);
#pragma unroll
                for (int mi = 0; mi < 2; mi++) {
                    MMA8(acc[mi][nj], aH[mi], bH);
                    MMA8(acc[mi][nj], aH[mi], bL);
                    MMA8(acc[mi][nj], aL[mi], bH);
                }
            }
        }
        __syncthreads();
    }

#pragma unroll
    for (int mi = 0; mi < 2; mi++) {
        int r0 = bm + wm + mi * 16 + gq;
#pragma unroll
        for (int nj = 0; nj < 8; nj++) {
            int cl = wn + nj * 8 + 2 * t4;
            float2 p0, p1;
            p0.x = acc[mi][nj][0]; p0.y = acc[mi][nj][1];
            p1.x = acc[mi][nj][2]; p1.y = acc[mi][nj][3];
            *(float2*)(C + (long)r0 * HW + bn + cl)       = p0;
            *(float2*)(C + (long)(r0 + 8) * HW + bn + cl) = p1;
        }
    }
}

// ---------------------------------------------------------------------------
// Row softmax over N=4096, written back tf32-rounded (P~ = tf32(exp/Z)).
// ---------------------------------------------------------------------------
__global__ __launch_bounds__(256) void softmax_kernel(float* __restrict__ S)
{
    __shared__ float row[HW];
    __shared__ float redbuf[8];
    const long base = (long)blockIdx.x * HW;
    const int tid = threadIdx.x;

    float m = -INFINITY;
    for (int i = tid; i < HW; i += 256) {
        float v = S[base + i];
        row[i] = v;
        m = fmaxf(m, v);
    }
#pragma unroll
    for (int o = 16; o; o >>= 1) m = fmaxf(m, __shfl_xor_sync(0xffffffffu, m, o));
    if ((tid & 31) == 0) redbuf[tid >> 5] = m;
    __syncthreads();
    if (tid < 32) {
        float v = (tid < 8) ? redbuf[tid] : -INFINITY;
#pragma unroll
        for (int o = 4; o; o >>= 1) v = fmaxf(v, __shfl_xor_sync(0xffffffffu, v, o));
        if (tid == 0) redbuf[0] = v;
    }
    __syncthreads();
    const float rowmax = redbuf[0];
    __syncthreads();

    float s = 0.0f;
    for (int i = tid; i < HW; i += 256) {
        float e = __expf(row[i] - rowmax);
        row[i] = e;
        s += e;
    }
#pragma unroll
    for (int o = 16; o; o >>= 1) s += __shfl_xor_sync(0xffffffffu, s, o);
    if ((tid & 31) == 0) redbuf[tid >> 5] = s;
    __syncthreads();
    if (tid < 32) {
        float v = (tid < 8) ? redbuf[tid] : 0.0f;
#pragma unroll
        for (int o = 4; o; o >>= 1) v += __shfl_xor_sync(0xffffffffu, v, o);
        if (tid == 0) redbuf[0] = v;
    }
    __syncthreads();
    const float inv = 1.0f / redbuf[0];
    for (int i = tid; i < HW; i += 256) S[base + i] = tf32f(row[i] * inv);
}

// ---------------------------------------------------------------------------
static float* sym_addr_f(const void* symbol)
{
    void* p = nullptr;
    cudaGetSymbolAddress(&p, symbol);
    return (float*)p;
}

extern "C" void kernel_launch(void* const* d_in, const int* in_sizes, int n_in,
                              void* d_out, int out_size)
{
    const float* content = (const float*)d_in[0];
    const float* style   = (const float*)d_in[1];
    const float* f_w     = (const float*)d_in[2];
    const float* f_b     = (const float*)d_in[3];
    const float* g_w     = (const float*)d_in[4];
    const float* g_b     = (const float*)d_in[5];
    const float* h_w     = (const float*)d_in[6];
    const float* h_b     = (const float*)d_in[7];
    const float* out_w   = (const float*)d_in[8];
    const float* out_b   = (const float*)d_in[9];
    float* out = (float*)d_out;

    float* xr   = sym_addr_f(g_xr);
    float* xr32 = sym_addr_f(g_xr32);
    float* f    = sym_addr_f(g_f);
    float* g    = sym_addr_f(g_g);
    float* h32  = sym_addr_f(g_h32);
    float* S    = sym_addr_f(g_S);
    float* o32  = sym_addr_f(g_o32);
    float* hw32 = sym_addr_f(g_hw32);
    float* ow32 = sym_addr_f(g_ow32);

    const long long sX = (long long)CIN * HW;
    const long long sF = (long long)C8 * HW;
    const long long sS = (long long)HW * HW;

    // 1. resize style -> xr (fp32) + xr32 (tf32)
    {
        long total = (long)BATCH * CIN * HW;
        resize_kernel<<<(unsigned)(total / 256), 256>>>(style, xr, xr32);
    }
    // 1b. round weights
    round_kernel<<<(CIN * CIN) / 256, 256>>>(h_w, hw32, CIN * CIN);
    round_kernel<<<(CIN * CIN) / 256, 256>>>(out_w, ow32, CIN * CIN);

    // 2/3. f, g convs (fp32)
    gemm64_kernel<<<dim3(HW / GBN, C8 / GBM, BATCH), 256>>>(
        f_w, content, f, f_b, C8, HW, CIN, sX, sF);
    gemm64_kernel<<<dim3(HW / GBN, C8 / GBM, BATCH), 256>>>(
        g_w, xr, g, g_b, C8, HW, CIN, sX, sF);

    // 4. h32 = round(hw32 @ xr32 + h_b)
    mma_pipe<false, true, true><<<dim3(CIN / TBM, HW / TBN, BATCH), 256>>>(
        hw32, xr32, h32, h_b, CIN, HW, CIN, 0, sX, sX);

    // 5. S = f^T g (3xtf32)
    s_gemm3_kernel<<<dim3(HW / TBM, HW / TBN, BATCH), 256>>>(
        f, g, S, sF, sF, sS);

    // 6. P~ = tf32(softmax rows), in place
    softmax_kernel<<<BATCH * HW, 256>>>(S);

    // 7. o32 = round(h32 @ P~^T)
    mma_pipe<true, false, true><<<dim3(CIN / TBM, HW / TBN, BATCH), 256>>>(
        h32, S, o32, nullptr, CIN, HW, HW, sX, sS, sX);

    // 8. out = ow32 @ o32 + out_b
    mma_pipe<false, true, false><<<dim3(CIN / TBM, HW / TBN, BATCH), 256>>>(
        ow32, o32, out, out_b, CIN, HW, CIN, 0, sX, sX);
}